// round 11
// baseline (speedup 1.0000x reference)
#include <cuda_runtime.h>

#define Dd  30
#define H1d 15
#define Tt  512
#define Bb  4096
#define EPW 4

typedef unsigned long long ull;

// scratch: u1 = Wih1*x + b (padded to 32), h2 sequence (padded to 32)
__device__ __align__(128) float g_u1[(size_t)Bb * Tt * 32];
__device__ __align__(128) float g_h2[(size_t)Bb * Tt * 32];

__device__ __forceinline__ void fma2(ull& d, ull a, ull b) {
    asm("fma.rn.f32x2 %0, %1, %2, %0;" : "+l"(d) : "l"(a), "l"(b));
}
__device__ __forceinline__ ull packf2(float lo, float hi) {
    ull r; asm("mov.b64 %0, {%1, %2};" : "=l"(r) : "f"(lo), "f"(hi)); return r;
}
__device__ __forceinline__ float2 unpackf2(ull v) {
    float2 r; asm("mov.b64 {%0, %1}, %2;" : "=f"(r.x), "=f"(r.y) : "l"(v)); return r;
}
__device__ __forceinline__ float fast_tanh(float x) {
    x = fminf(15.f, fmaxf(-15.f, x));
    float e = __expf(2.f * x);
    return __fdividef(e - 1.f, e + 1.f);
}

// 30-elem dot: buf is a 16B-aligned 32-float row, Wp = 15 packed f32x2 weights
__device__ __forceinline__ float dot30(const float* __restrict__ buf, const ull* Wp) {
    const ulonglong2* vp = (const ulonglong2*)buf;
    ull a0 = 0, a1 = 0;
#pragma unroll
    for (int i = 0; i < 7; i++) {
        ulonglong2 v = vp[i];
        fma2(a0, Wp[2 * i],     v.x);
        fma2(a1, Wp[2 * i + 1], v.y);
    }
    fma2(a0, Wp[14], ((const ull*)buf)[14]);
    float2 f0 = unpackf2(a0), f1 = unpackf2(a1);
    return (f0.x + f0.y) + (f1.x + f1.y);
}
// 16-elem dot (entries 15..31 of buf multiplied by zero-padded weights)
__device__ __forceinline__ float dot16(const float* __restrict__ buf, const ull* Wp) {
    const ulonglong2* vp = (const ulonglong2*)buf;
    ull a0 = 0, a1 = 0;
#pragma unroll
    for (int i = 0; i < 4; i++) {
        ulonglong2 v = vp[i];
        fma2(a0, Wp[2 * i],     v.x);
        fma2(a1, Wp[2 * i + 1], v.y);
    }
    float2 f0 = unpackf2(a0), f1 = unpackf2(a1);
    return (f0.x + f0.y) + (f1.x + f1.y);
}

// ---------------- Kernel A: u1 = Wih1*x + bih1 + bhh1 (fully parallel) ----------------
__global__ void __launch_bounds__(32)
proj_kernel(const float* __restrict__ x, const float* __restrict__ Wih1,
            const float* __restrict__ bih1, const float* __restrict__ bhh1)
{
    __shared__ __align__(16) float xs[2][32];
    const int lane = threadIdx.x;
    const int b = blockIdx.x;
    const bool rowv = (lane < Dd);

    ull Wp[15];
    const ull* w = (const ull*)(Wih1 + lane * Dd);
#pragma unroll
    for (int i = 0; i < 15; i++) Wp[i] = rowv ? w[i] : 0ull;
    const float bsum = rowv ? (bih1[lane] + bhh1[lane]) : 0.f;

    const float* __restrict__ xb = x + (size_t)b * Tt * Dd;
    float* __restrict__ ub = g_u1 + (size_t)b * Tt * 32;

    xs[0][lane] = rowv ? __ldg(xb + lane) : 0.f;
    float xn = rowv ? __ldg(xb + Dd + lane) : 0.f;
    __syncwarp();

    for (int t = 0; t < Tt; t++) {
        const int p = t & 1;
        float u = dot30(xs[p], Wp) + bsum;     // exact 0 on lanes >= 30
        ub[t * 32 + lane] = u;
        xs[1 - p][lane] = xn;
        xn = (rowv && t + 2 < Tt) ? __ldg(xb + (size_t)(t + 2) * Dd + lane) : 0.f;
        __syncwarp();
    }
}

// ---------------- Kernel B: the serial recurrences only ----------------
__global__ void __launch_bounds__(32)
recur_kernel(const float* __restrict__ Whh1,
             const float* __restrict__ Wih2, const float* __restrict__ Whh2,
             const float* __restrict__ bih2, const float* __restrict__ bhh2)
{
    __shared__ __align__(16) float h1sm[EPW][2][32], h2sm[EPW][2][32];
    const int lane = threadIdx.x;
    const bool rowv = (lane < Dd);

    ull Whh1p[15], Wih2p[15], Whh2p[15];
    {
        const ull* w1 = (const ull*)(Whh1 + lane * Dd);
        const ull* w2 = (const ull*)(Wih2 + lane * Dd);
        const ull* w3 = (const ull*)(Whh2 + lane * Dd);
#pragma unroll
        for (int i = 0; i < 15; i++) {
            Whh1p[i] = rowv ? w1[i] : 0ull;
            Wih2p[i] = rowv ? w2[i] : 0ull;
            Whh2p[i] = rowv ? w3[i] : 0ull;
        }
    }
    const float bs2r = rowv ? (bih2[lane] + bhh2[lane]) : 0.f;

    const int b0 = blockIdx.x * EPW;
    const float* __restrict__ ub[EPW];
    float* __restrict__ hb[EPW];
    float u1cur[EPW], u1nxt[EPW];
#pragma unroll
    for (int e = 0; e < EPW; e++) {
        ub[e] = g_u1 + (size_t)(b0 + e) * Tt * 32;
        hb[e] = g_h2 + (size_t)(b0 + e) * Tt * 32;
        h1sm[e][0][lane] = 0.f; h1sm[e][1][lane] = 0.f;
        h2sm[e][0][lane] = 0.f; h2sm[e][1][lane] = 0.f;
        u1cur[e] = __ldg(ub[e] + lane);
        u1nxt[e] = __ldg(ub[e] + 32 + lane);
    }
    __syncwarp();

    for (int t = 0; t < Tt; t++) {
        const int p = t & 1;
        float pre2[EPW];

        // stage 1: h1' = tanh(u1 + Whh1*h1); pre2 = bs2 + Whh2*h2 (independent -> ILP)
#pragma unroll
        for (int e = 0; e < EPW; e++) {
            float sA = dot30(h1sm[e][p], Whh1p);
            float sB = dot30(h2sm[e][p], Whh2p);
            h1sm[e][1 - p][lane] = fast_tanh(sA + u1cur[e]);
            pre2[e] = sB + bs2r;
        }
        __syncwarp();

        // stage 2: h2' = tanh(pre2 + Wih2*h1'); stream h2 out; advance u1 pipeline
#pragma unroll
        for (int e = 0; e < EPW; e++) {
            float sC = dot30(h1sm[e][1 - p], Wih2p);
            float h2n = fast_tanh(pre2[e] + sC);
            h2sm[e][1 - p][lane] = h2n;
            hb[e][t * 32 + lane] = h2n;
            u1cur[e] = u1nxt[e];
            u1nxt[e] = (t + 2 < Tt) ? __ldg(ub[e] + (size_t)(t + 2) * 32 + lane) : 0.f;
        }
        __syncwarp();
    }
}

// ---------------- Kernel C: MLP head (fully parallel over (b,t)) ----------------
__global__ void __launch_bounds__(32)
mlp_kernel(const float* __restrict__ W1, const float* __restrict__ b1,
           const float* __restrict__ W2, const float* __restrict__ b2,
           const float* __restrict__ W3, const float* __restrict__ b3,
           float* __restrict__ out)
{
    __shared__ __align__(16) float z1sm[32], ys[32];
    const int lane = threadIdx.x;
    const int b = blockIdx.x;
    const bool mlpv = (lane < H1d);

    ull W1p[15], W2p[8];
    {
        const ull* w1 = (const ull*)(W1 + lane * Dd);
#pragma unroll
        for (int i = 0; i < 15; i++) W1p[i] = mlpv ? w1[i] : 0ull;
#pragma unroll
        for (int i = 0; i < 7; i++)
            W2p[i] = mlpv ? packf2(W2[lane * H1d + 2 * i], W2[lane * H1d + 2 * i + 1]) : 0ull;
        W2p[7] = mlpv ? packf2(W2[lane * H1d + 14], 0.f) : 0ull;
    }
    const float W3r = mlpv ? W3[lane] : 0.f;
    const float b1r = mlpv ? b1[lane] : 0.f;
    const float b2r = mlpv ? b2[lane] : 0.f;
    const float b3v = b3[0];

    const float* __restrict__ hrow = g_h2 + (size_t)b * Tt * 32;
    float* __restrict__ ob = out + (size_t)b * Tt;

    for (int t = 0; t < Tt; t++) {
        // z1 = tanh(W1*h2 + b1); uniform LDG.128 broadcast of the h2 row
        float z1 = fast_tanh(dot30(hrow + (size_t)t * 32, W1p) + b1r);  // exact 0 on lanes >= 15
        z1sm[lane] = z1;
        __syncwarp();
        // z2 = tanh(W2*z1 + b2)
        float z2 = fast_tanh(dot16(z1sm, W2p) + b2r);
        __syncwarp();
        // y = W3*z2 + b3 via butterfly over lanes 0..15 (lanes >=15 contribute exact 0)
        float s = W3r * z2;
#pragma unroll
        for (int off = 8; off >= 1; off >>= 1)
            s += __shfl_xor_sync(0xffffffffu, s, off);
        if (lane == 0) ys[t & 31] = s + b3v;

        if ((t & 31) == 31) {
            __syncwarp();
            ob[(t - 31) + lane] = ys[lane];
            __syncwarp();
        }
    }
}

extern "C" void kernel_launch(void* const* d_in, const int* in_sizes, int n_in,
                              void* d_out, int out_size)
{
    const float* x    = (const float*)d_in[0];
    const float* Wih1 = (const float*)d_in[1];
    const float* Whh1 = (const float*)d_in[2];
    const float* bih1 = (const float*)d_in[3];
    const float* bhh1 = (const float*)d_in[4];
    const float* Wih2 = (const float*)d_in[5];
    const float* Whh2 = (const float*)d_in[6];
    const float* bih2 = (const float*)d_in[7];
    const float* bhh2 = (const float*)d_in[8];
    const float* W1   = (const float*)d_in[9];
    const float* b1   = (const float*)d_in[10];
    const float* W2   = (const float*)d_in[11];
    const float* b2   = (const float*)d_in[12];
    const float* W3   = (const float*)d_in[13];
    const float* b3   = (const float*)d_in[14];

    int B = in_sizes[0] / (Tt * Dd);   // 4096
    proj_kernel<<<B, 32>>>(x, Wih1, bih1, bhh1);
    recur_kernel<<<B / EPW, 32>>>(Whh1, Wih2, Whh2, bih2, bhh2);
    mlp_kernel<<<B, 32>>>(W1, b1, W2, b2, W3, b3, (float*)d_out);
}

// round 12
// speedup vs baseline: 1.7938x; 1.7938x over previous
#include <cuda_runtime.h>

#define Dd  30
#define H1d 15
#define Tt  512
#define Bb  4096
#define EPW 4

typedef unsigned long long ull;

// scratch: u1 = Wih1*x + b (padded to 32 floats/row), h2 sequence (padded to 32)
__device__ __align__(128) float g_u1[(size_t)Bb * Tt * 32];
__device__ __align__(128) float g_h2[(size_t)Bb * Tt * 32];

__device__ __forceinline__ void fma2(ull& d, ull a, ull b) {
    asm("fma.rn.f32x2 %0, %1, %2, %0;" : "+l"(d) : "l"(a), "l"(b));
}
__device__ __forceinline__ ull packf2(float lo, float hi) {
    ull r; asm("mov.b64 %0, {%1, %2};" : "=l"(r) : "f"(lo), "f"(hi)); return r;
}
__device__ __forceinline__ float2 unpackf2(ull v) {
    float2 r; asm("mov.b64 {%0, %1}, %2;" : "=f"(r.x), "=f"(r.y) : "l"(v)); return r;
}
__device__ __forceinline__ float fast_tanh(float x) {
    x = fminf(15.f, fmaxf(-15.f, x));
    float e = __expf(2.f * x);
    return __fdividef(e - 1.f, e + 1.f);
}

// 30-elem dot: buf = 16B-aligned 32-float row, Wp = 15 packed f32x2 weights
__device__ __forceinline__ float dot30(const float* __restrict__ buf, const ull* Wp) {
    const ulonglong2* vp = (const ulonglong2*)buf;
    ull a0 = 0, a1 = 0;
#pragma unroll
    for (int i = 0; i < 7; i++) {
        ulonglong2 v = vp[i];
        fma2(a0, Wp[2 * i],     v.x);
        fma2(a1, Wp[2 * i + 1], v.y);
    }
    fma2(a0, Wp[14], ((const ull*)buf)[14]);
    float2 f0 = unpackf2(a0), f1 = unpackf2(a1);
    return (f0.x + f0.y) + (f1.x + f1.y);
}
__device__ __forceinline__ float dot16(const float* __restrict__ buf, const ull* Wp) {
    const ulonglong2* vp = (const ulonglong2*)buf;
    ull a0 = 0, a1 = 0;
#pragma unroll
    for (int i = 0; i < 4; i++) {
        ulonglong2 v = vp[i];
        fma2(a0, Wp[2 * i],     v.x);
        fma2(a1, Wp[2 * i + 1], v.y);
    }
    float2 f0 = unpackf2(a0), f1 = unpackf2(a1);
    return (f0.x + f0.y) + (f1.x + f1.y);
}

#define PCH 4    // t-chunks per batch in proj  -> chunk = 128 steps
#define MCH 16   // t-chunks per batch in mlp   -> chunk = 32 steps

// ---------------- Kernel A: u1 = Wih1*x + bih1 + bhh1 (parallel over b AND t) ----------------
__global__ void __launch_bounds__(128)
proj_kernel(const float* __restrict__ x, const float* __restrict__ Wih1,
            const float* __restrict__ bih1, const float* __restrict__ bhh1)
{
    __shared__ __align__(16) float xs[4][2][32];
    const int lane = threadIdx.x & 31;
    const int wrp  = threadIdx.x >> 5;
    const int gid  = blockIdx.x * 4 + wrp;
    const int b    = gid >> 2;
    const int t0   = (gid & 3) * (Tt / PCH);
    const bool rowv = (lane < Dd);

    ull Wp[15];
    const ull* w = (const ull*)(Wih1 + lane * Dd);
#pragma unroll
    for (int i = 0; i < 15; i++) Wp[i] = rowv ? w[i] : 0ull;
    const float bsum = rowv ? (bih1[lane] + bhh1[lane]) : 0.f;

    const float* __restrict__ xb = x + (size_t)b * Tt * Dd + (size_t)t0 * Dd;
    float* __restrict__ ub = g_u1 + (size_t)b * Tt * 32 + (size_t)t0 * 32;
    float (*xbuf)[32] = xs[wrp];

    xbuf[0][lane] = rowv ? __ldg(xb + lane) : 0.f;
    float xn = rowv ? __ldg(xb + Dd + lane) : 0.f;
    __syncwarp();

    for (int t = 0; t < Tt / PCH; t++) {
        const int p = t & 1;
        float u = dot30(xbuf[p], Wp) + bsum;     // exact 0 on lanes >= 30
        ub[t * 32 + lane] = u;
        xbuf[1 - p][lane] = xn;
        xn = (rowv && t + 2 < Tt / PCH) ? __ldg(xb + (size_t)(t + 2) * Dd + lane) : 0.f;
        __syncwarp();
    }
}

// ---------------- Kernel B: skew-pipelined recurrences (ONE sync stage per step) ----------------
__global__ void __launch_bounds__(32)
recur_kernel(const float* __restrict__ Whh1,
             const float* __restrict__ Wih2, const float* __restrict__ Whh2,
             const float* __restrict__ bih2, const float* __restrict__ bhh2)
{
    __shared__ __align__(16) float h1sm[EPW][2][32], h2sm[EPW][2][32];
    const int lane = threadIdx.x;
    const bool rowv = (lane < Dd);

    ull Whh1p[15], Wih2p[15], Whh2p[15];
    {
        const ull* w1 = (const ull*)(Whh1 + lane * Dd);
        const ull* w2 = (const ull*)(Wih2 + lane * Dd);
        const ull* w3 = (const ull*)(Whh2 + lane * Dd);
#pragma unroll
        for (int i = 0; i < 15; i++) {
            Whh1p[i] = rowv ? w1[i] : 0ull;
            Wih2p[i] = rowv ? w2[i] : 0ull;
            Whh2p[i] = rowv ? w3[i] : 0ull;
        }
    }
    const float bs2r = rowv ? (bih2[lane] + bhh2[lane]) : 0.f;

    const int b0 = blockIdx.x * EPW;
    const float* __restrict__ ub[EPW];
    float* __restrict__ hb[EPW];
    float u1c[EPW], u1n1[EPW], u1n2[EPW];
#pragma unroll
    for (int e = 0; e < EPW; e++) {
        ub[e] = g_u1 + (size_t)(b0 + e) * Tt * 32;
        hb[e] = g_h2 + (size_t)(b0 + e) * Tt * 32;
        h1sm[e][0][lane] = 0.f; h1sm[e][1][lane] = 0.f;
        h2sm[e][0][lane] = 0.f; h2sm[e][1][lane] = 0.f;
        u1c[e]  = __ldg(ub[e] + lane);
        u1n1[e] = __ldg(ub[e] + 32 + lane);
        u1n2[e] = __ldg(ub[e] + 64 + lane);
    }
    __syncwarp();

    // ---- peeled s = 0: h1[0] = tanh(u1[0]) ----
#pragma unroll
    for (int e = 0; e < EPW; e++) {
        h1sm[e][0][lane] = fast_tanh(u1c[e]);
        u1c[e] = u1n1[e]; u1n1[e] = u1n2[e];
        u1n2[e] = __ldg(ub[e] + 3 * 32 + lane);
    }
    __syncwarp();

    // ---- hot loop s = 1..511: one stage computes h1[s] AND h2[s-1] ----
    for (int s = 1; s < Tt; s++) {
        const int p  = s & 1;       // write parity for h1[s]; read h2[s-2] here
        const int q  = 1 - p;       // read parity for h1[s-1]; write parity for h2[s-1]
#pragma unroll
        for (int e = 0; e < EPW; e++) {
            const float* h1prev = h1sm[e][q];
            float sA = dot30(h1prev,     Whh1p);   // -> h1[s]
            float sB = dot30(h1prev,     Wih2p);   // -> h2[s-1]
            float sC = dot30(h2sm[e][p], Whh2p);   // h2[s-2] contribution
            float h1n = fast_tanh(sA + u1c[e]);
            float h2n = fast_tanh(sB + sC + bs2r);
            h1sm[e][p][lane] = h1n;
            h2sm[e][q][lane] = h2n;
            hb[e][(size_t)(s - 1) * 32 + lane] = h2n;   // stream h2[s-1] out
            u1c[e] = u1n1[e]; u1n1[e] = u1n2[e];
            u1n2[e] = (s + 3 < Tt) ? __ldg(ub[e] + (size_t)(s + 3) * 32 + lane) : 0.f;
        }
        __syncwarp();
    }

    // ---- peeled s = 512: h2[511] ----
#pragma unroll
    for (int e = 0; e < EPW; e++) {
        float sB = dot30(h1sm[e][1], Wih2p);   // h1[511], parity 511&1 = 1
        float sC = dot30(h2sm[e][0], Whh2p);   // h2[510], parity 512&1 = 0
        hb[e][(size_t)(Tt - 1) * 32 + lane] = fast_tanh(sB + sC + bs2r);
    }
}

// ---------------- Kernel C: MLP head (parallel over b AND t) ----------------
__global__ void __launch_bounds__(128)
mlp_kernel(const float* __restrict__ W1, const float* __restrict__ b1,
           const float* __restrict__ W2, const float* __restrict__ b2,
           const float* __restrict__ W3, const float* __restrict__ b3,
           float* __restrict__ out)
{
    __shared__ __align__(16) float h2s[4][2][32], z1s[4][32], ys[4][32];
    const int lane = threadIdx.x & 31;
    const int wrp  = threadIdx.x >> 5;
    const int gid  = blockIdx.x * 4 + wrp;
    const int b    = gid >> 4;
    const int t0   = (gid & 15) * (Tt / MCH);
    const bool mlpv = (lane < H1d);

    ull W1p[15], W2p[8];
    {
        const ull* w1 = (const ull*)(W1 + lane * Dd);
#pragma unroll
        for (int i = 0; i < 15; i++) W1p[i] = mlpv ? w1[i] : 0ull;
#pragma unroll
        for (int i = 0; i < 7; i++)
            W2p[i] = mlpv ? packf2(W2[lane * H1d + 2 * i], W2[lane * H1d + 2 * i + 1]) : 0ull;
        W2p[7] = mlpv ? packf2(W2[lane * H1d + 14], 0.f) : 0ull;
    }
    const float W3r = mlpv ? W3[lane] : 0.f;
    const float b1r = mlpv ? b1[lane] : 0.f;
    const float b2r = mlpv ? b2[lane] : 0.f;
    const float b3v = b3[0];

    const float* __restrict__ hrow = g_h2 + (size_t)b * Tt * 32 + (size_t)t0 * 32;
    float* __restrict__ ob = out + (size_t)b * Tt + t0;

    float (*hbuf)[32] = h2s[wrp];
    hbuf[0][lane] = __ldg(hrow + lane);            // coalesced row prefetch
    float hn = __ldg(hrow + 32 + lane);
    __syncwarp();

    for (int i = 0; i < Tt / MCH; i++) {
        const int p = i & 1;
        // z1 = tanh(W1*h2 + b1): uniform LDS broadcast of staged row
        float z1 = fast_tanh(dot30(hbuf[p], W1p) + b1r);   // exact 0 on lanes >= 15
        z1s[wrp][lane] = z1;
        hbuf[1 - p][lane] = hn;                            // stage next row (independent)
        __syncwarp();
        // z2 = tanh(W2*z1 + b2)
        float z2 = fast_tanh(dot16(z1s[wrp], W2p) + b2r);
        // y = W3*z2 + b3, butterfly over 16 lanes (lanes >= 15 contribute exact 0)
        float s = W3r * z2;
#pragma unroll
        for (int off = 8; off >= 1; off >>= 1)
            s += __shfl_xor_sync(0xffffffffu, s, off);
        if (lane == 0) ys[wrp][i] = s + b3v;
        hn = (i + 2 < Tt / MCH) ? __ldg(hrow + (size_t)(i + 2) * 32 + lane) : 0.f;
        __syncwarp();
    }
    ob[lane] = ys[wrp][lane];   // coalesced 32-wide flush
}

extern "C" void kernel_launch(void* const* d_in, const int* in_sizes, int n_in,
                              void* d_out, int out_size)
{
    const float* x    = (const float*)d_in[0];
    const float* Wih1 = (const float*)d_in[1];
    const float* Whh1 = (const float*)d_in[2];
    const float* bih1 = (const float*)d_in[3];
    const float* bhh1 = (const float*)d_in[4];
    const float* Wih2 = (const float*)d_in[5];
    const float* Whh2 = (const float*)d_in[6];
    const float* bih2 = (const float*)d_in[7];
    const float* bhh2 = (const float*)d_in[8];
    const float* W1   = (const float*)d_in[9];
    const float* b1   = (const float*)d_in[10];
    const float* W2   = (const float*)d_in[11];
    const float* b2   = (const float*)d_in[12];
    const float* W3   = (const float*)d_in[13];
    const float* b3   = (const float*)d_in[14];

    int B = in_sizes[0] / (Tt * Dd);   // 4096
    proj_kernel<<<B * PCH / 4, 128>>>(x, Wih1, bih1, bhh1);
    recur_kernel<<<B / EPW, 32>>>(Whh1, Wih2, Whh2, bih2, bhh2);
    mlp_kernel<<<B * MCH / 4, 128>>>(W1, b1, W2, b2, W3, b3, (float*)d_out);
}

// round 13
// speedup vs baseline: 1.8949x; 1.0564x over previous
#include <cuda_runtime.h>

#define Dd  30
#define H1d 15
#define Tt  512
#define Bb  4096

typedef unsigned long long ull;

// scratch: u1 = Wih1*x + b (padded to 32 floats/row), h2 sequence (padded to 32)
__device__ __align__(128) float g_u1[(size_t)Bb * Tt * 32];
__device__ __align__(128) float g_h2[(size_t)Bb * Tt * 32];

__device__ __forceinline__ void fma2(ull& d, ull a, ull b) {
    asm("fma.rn.f32x2 %0, %1, %2, %0;" : "+l"(d) : "l"(a), "l"(b));
}
__device__ __forceinline__ ull packf2(float lo, float hi) {
    ull r; asm("mov.b64 %0, {%1, %2};" : "=l"(r) : "f"(lo), "f"(hi)); return r;
}
__device__ __forceinline__ float2 unpackf2(ull v) {
    float2 r; asm("mov.b64 {%0, %1}, %2;" : "=f"(r.x), "=f"(r.y) : "l"(v)); return r;
}
__device__ __forceinline__ float fast_tanh(float x) {
    x = fminf(15.f, fmaxf(-15.f, x));
    float e = __expf(2.f * x);
    return __fdividef(e - 1.f, e + 1.f);
}

// single 30-elem dot (buf = 16B-aligned 32-float row, Wp = 15 packed f32x2)
__device__ __forceinline__ float dot30(const float* __restrict__ buf, const ull* Wp) {
    const ulonglong2* vp = (const ulonglong2*)buf;
    ull a0 = 0, a1 = 0;
#pragma unroll
    for (int i = 0; i < 7; i++) {
        ulonglong2 v = vp[i];
        fma2(a0, Wp[2 * i],     v.x);
        fma2(a1, Wp[2 * i + 1], v.y);
    }
    fma2(a0, Wp[14], ((const ull*)buf)[14]);
    float2 f0 = unpackf2(a0), f1 = unpackf2(a1);
    return (f0.x + f0.y) + (f1.x + f1.y);
}
// two 30-elem dots sharing ONE load of buf (saves 8 LDS per call)
__device__ __forceinline__ float2 dot30_dual(const float* __restrict__ buf,
                                             const ull* Wa, const ull* Wb) {
    const ulonglong2* vp = (const ulonglong2*)buf;
    ull a0 = 0, a1 = 0, b0 = 0, b1 = 0;
#pragma unroll
    for (int i = 0; i < 7; i++) {
        ulonglong2 v = vp[i];
        fma2(a0, Wa[2 * i],     v.x);
        fma2(b0, Wb[2 * i],     v.x);
        fma2(a1, Wa[2 * i + 1], v.y);
        fma2(b1, Wb[2 * i + 1], v.y);
    }
    ull vl = ((const ull*)buf)[14];
    fma2(a0, Wa[14], vl);
    fma2(b0, Wb[14], vl);
    float2 fa0 = unpackf2(a0), fa1 = unpackf2(a1);
    float2 fb0 = unpackf2(b0), fb1 = unpackf2(b1);
    return make_float2((fa0.x + fa0.y) + (fa1.x + fa1.y),
                       (fb0.x + fb0.y) + (fb1.x + fb1.y));
}
__device__ __forceinline__ float dot16(const float* __restrict__ buf, const ull* Wp) {
    const ulonglong2* vp = (const ulonglong2*)buf;
    ull a0 = 0, a1 = 0;
#pragma unroll
    for (int i = 0; i < 4; i++) {
        ulonglong2 v = vp[i];
        fma2(a0, Wp[2 * i],     v.x);
        fma2(a1, Wp[2 * i + 1], v.y);
    }
    float2 f0 = unpackf2(a0), f1 = unpackf2(a1);
    return (f0.x + f0.y) + (f1.x + f1.y);
}

#define PCH 4    // t-chunks per batch in proj  -> chunk = 128 steps
#define MCH 16   // t-chunks per batch in mlp   -> chunk = 32 steps

// ---------------- Kernel A: u1 = Wih1*x + bih1 + bhh1 (parallel over b AND t) ----------------
__global__ void __launch_bounds__(128)
proj_kernel(const float* __restrict__ x, const float* __restrict__ Wih1,
            const float* __restrict__ bih1, const float* __restrict__ bhh1)
{
    __shared__ __align__(16) float xs[4][2][32];
    const int lane = threadIdx.x & 31;
    const int wrp  = threadIdx.x >> 5;
    const int gid  = blockIdx.x * 4 + wrp;
    const int b    = gid >> 2;
    const int t0   = (gid & 3) * (Tt / PCH);
    const bool rowv = (lane < Dd);

    ull Wp[15];
    const ull* w = (const ull*)(Wih1 + lane * Dd);
#pragma unroll
    for (int i = 0; i < 15; i++) Wp[i] = rowv ? w[i] : 0ull;
    const float bsum = rowv ? (bih1[lane] + bhh1[lane]) : 0.f;

    const float* __restrict__ xb = x + (size_t)b * Tt * Dd + (size_t)t0 * Dd;
    float* __restrict__ ub = g_u1 + (size_t)b * Tt * 32 + (size_t)t0 * 32;
    float (*xbuf)[32] = xs[wrp];

    xbuf[0][lane] = rowv ? __ldg(xb + lane) : 0.f;
    float xn = rowv ? __ldg(xb + Dd + lane) : 0.f;
    __syncwarp();

    for (int t = 0; t < Tt / PCH; t++) {
        const int p = t & 1;
        float u = dot30(xbuf[p], Wp) + bsum;     // exact 0 on lanes >= 30
        ub[t * 32 + lane] = u;
        xbuf[1 - p][lane] = xn;
        xn = (rowv && t + 2 < Tt / PCH) ? __ldg(xb + (size_t)(t + 2) * Dd + lane) : 0.f;
        __syncwarp();
    }
}

// ---------------- Kernel B: skew-pipelined recurrences, 1 batch elem / warp ----------------
__global__ void __launch_bounds__(32)
recur_kernel(const float* __restrict__ Whh1,
             const float* __restrict__ Wih2, const float* __restrict__ Whh2,
             const float* __restrict__ bih2, const float* __restrict__ bhh2)
{
    __shared__ __align__(16) float h1sm[2][32], h2sm[2][32];
    const int lane = threadIdx.x;
    const bool rowv = (lane < Dd);

    ull Whh1p[15], Wih2p[15], Whh2p[15];
    {
        const ull* w1 = (const ull*)(Whh1 + lane * Dd);
        const ull* w2 = (const ull*)(Wih2 + lane * Dd);
        const ull* w3 = (const ull*)(Whh2 + lane * Dd);
#pragma unroll
        for (int i = 0; i < 15; i++) {
            Whh1p[i] = rowv ? w1[i] : 0ull;
            Wih2p[i] = rowv ? w2[i] : 0ull;
            Whh2p[i] = rowv ? w3[i] : 0ull;
        }
    }
    const float bs2r = rowv ? (bih2[lane] + bhh2[lane]) : 0.f;

    const int b = blockIdx.x;
    const float* __restrict__ ub = g_u1 + (size_t)b * Tt * 32;
    float* __restrict__ hb = g_h2 + (size_t)b * Tt * 32;

    h1sm[0][lane] = 0.f; h1sm[1][lane] = 0.f;
    h2sm[0][lane] = 0.f; h2sm[1][lane] = 0.f;
    float u1c  = __ldg(ub + lane);
    float u1n1 = __ldg(ub + 32 + lane);
    float u1n2 = __ldg(ub + 64 + lane);
    __syncwarp();

    // ---- peeled s = 0: h1[0] = tanh(u1[0]) ----
    h1sm[0][lane] = fast_tanh(u1c);
    u1c = u1n1; u1n1 = u1n2;
    u1n2 = __ldg(ub + 3 * 32 + lane);
    __syncwarp();

    // ---- hot loop s = 1..511: one stage computes h1[s] AND h2[s-1] ----
#pragma unroll 2
    for (int s = 1; s < Tt; s++) {
        const int p = s & 1;        // write parity for h1[s]; read h2[s-2]
        const int q = 1 - p;        // read parity for h1[s-1]; write parity for h2[s-1]
        float2 sAB = dot30_dual(h1sm[q], Whh1p, Wih2p);   // h1[s-1] row loaded once
        float  sC  = dot30(h2sm[p], Whh2p);               // h2[s-2] contribution
        float h1n = fast_tanh(sAB.x + u1c);
        float h2n = fast_tanh(sAB.y + sC + bs2r);
        h1sm[p][lane] = h1n;
        h2sm[q][lane] = h2n;
        hb[(size_t)(s - 1) * 32 + lane] = h2n;            // stream h2[s-1] out
        u1c = u1n1; u1n1 = u1n2;
        u1n2 = (s + 3 < Tt) ? __ldg(ub + (size_t)(s + 3) * 32 + lane) : 0.f;
        __syncwarp();
    }

    // ---- peeled s = 512: h2[511] ----
    {
        float sB = dot30(h1sm[1], Wih2p);   // h1[511], parity 511&1 = 1
        float sC = dot30(h2sm[0], Whh2p);   // h2[510], parity 512&1 = 0
        hb[(size_t)(Tt - 1) * 32 + lane] = fast_tanh(sB + sC + bs2r);
    }
}

// ---------------- Kernel C: MLP head (parallel over b AND t) ----------------
__global__ void __launch_bounds__(128)
mlp_kernel(const float* __restrict__ W1, const float* __restrict__ b1,
           const float* __restrict__ W2, const float* __restrict__ b2,
           const float* __restrict__ W3, const float* __restrict__ b3,
           float* __restrict__ out)
{
    __shared__ __align__(16) float h2s[4][2][32], z1s[4][32], ys[4][32];
    const int lane = threadIdx.x & 31;
    const int wrp  = threadIdx.x >> 5;
    const int gid  = blockIdx.x * 4 + wrp;
    const int b    = gid >> 4;
    const int t0   = (gid & 15) * (Tt / MCH);
    const bool mlpv = (lane < H1d);

    ull W1p[15], W2p[8];
    {
        const ull* w1 = (const ull*)(W1 + lane * Dd);
#pragma unroll
        for (int i = 0; i < 15; i++) W1p[i] = mlpv ? w1[i] : 0ull;
#pragma unroll
        for (int i = 0; i < 7; i++)
            W2p[i] = mlpv ? packf2(W2[lane * H1d + 2 * i], W2[lane * H1d + 2 * i + 1]) : 0ull;
        W2p[7] = mlpv ? packf2(W2[lane * H1d + 14], 0.f) : 0ull;
    }
    const float W3r = mlpv ? W3[lane] : 0.f;
    const float b1r = mlpv ? b1[lane] : 0.f;
    const float b2r = mlpv ? b2[lane] : 0.f;
    const float b3v = b3[0];

    const float* __restrict__ hrow = g_h2 + (size_t)b * Tt * 32 + (size_t)t0 * 32;
    float* __restrict__ ob = out + (size_t)b * Tt + t0;

    float (*hbuf)[32] = h2s[wrp];
    hbuf[0][lane] = __ldg(hrow + lane);            // coalesced row prefetch
    float hn = __ldg(hrow + 32 + lane);
    __syncwarp();

    for (int i = 0; i < Tt / MCH; i++) {
        const int p = i & 1;
        // z1 = tanh(W1*h2 + b1): uniform LDS broadcast of staged row
        float z1 = fast_tanh(dot30(hbuf[p], W1p) + b1r);   // exact 0 on lanes >= 15
        z1s[wrp][lane] = z1;
        hbuf[1 - p][lane] = hn;                            // stage next row (independent)
        __syncwarp();
        // z2 = tanh(W2*z1 + b2)
        float z2 = fast_tanh(dot16(z1s[wrp], W2p) + b2r);
        // y = W3*z2 + b3, butterfly over 16 lanes (lanes >= 15 contribute exact 0)
        float s = W3r * z2;
#pragma unroll
        for (int off = 8; off >= 1; off >>= 1)
            s += __shfl_xor_sync(0xffffffffu, s, off);
        if (lane == 0) ys[wrp][i] = s + b3v;
        hn = (i + 2 < Tt / MCH) ? __ldg(hrow + (size_t)(i + 2) * 32 + lane) : 0.f;
        __syncwarp();
    }
    ob[lane] = ys[wrp][lane];   // coalesced 32-wide flush
}

extern "C" void kernel_launch(void* const* d_in, const int* in_sizes, int n_in,
                              void* d_out, int out_size)
{
    const float* x    = (const float*)d_in[0];
    const float* Wih1 = (const float*)d_in[1];
    const float* Whh1 = (const float*)d_in[2];
    const float* bih1 = (const float*)d_in[3];
    const float* bhh1 = (const float*)d_in[4];
    const float* Wih2 = (const float*)d_in[5];
    const float* Whh2 = (const float*)d_in[6];
    const float* bih2 = (const float*)d_in[7];
    const float* bhh2 = (const float*)d_in[8];
    const float* W1   = (const float*)d_in[9];
    const float* b1   = (const float*)d_in[10];
    const float* W2   = (const float*)d_in[11];
    const float* b2   = (const float*)d_in[12];
    const float* W3   = (const float*)d_in[13];
    const float* b3   = (const float*)d_in[14];

    int B = in_sizes[0] / (Tt * Dd);   // 4096
    proj_kernel<<<B * PCH / 4, 128>>>(x, Wih1, bih1, bhh1);
    recur_kernel<<<B, 32>>>(Whh1, Wih2, Whh2, bih2, bhh2);
    mlp_kernel<<<B * MCH / 4, 128>>>(W1, b1, W2, b2, W3, b3, (float*)d_out);
}